// round 9
// baseline (speedup 1.0000x reference)
#include <cuda_runtime.h>

#define HH 1025
#define WW 1024
#define NIMG 4
#define RAD 15
#define KW 31

// scratch for harmonic (time-direction) medians
__device__ float g_harm[NIMG * HH * WW];

__device__ __forceinline__ void cas_asc(float &x, float &y) {
    float lo = fminf(x, y);
    float hi = fmaxf(x, y);
    x = lo; y = hi;
}

// bitonic sort of 32 floats ascending (a[31] is +INF sentinel)
__device__ __forceinline__ void sort32(float a[32]) {
#pragma unroll
    for (int k = 2; k <= 32; k <<= 1)
#pragma unroll
        for (int j = k >> 1; j > 0; j >>= 1)
#pragma unroll
            for (int i = 0; i < 32; ++i) {
                int l = i ^ j;
                if (l > i) {
                    if ((i & k) == 0) cas_asc(a[i], a[l]);
                    else              cas_asc(a[l], a[i]);
                }
            }
}

// sorted window a[0..30]; remove vold (bitwise present), insert vnew.
// delete: c[i] = (a[i] < vold) ? a[i] : a[i+1]   (monotone predicate; exact)
// insert: r[i] = max(c[i-1], min(c[i], vnew))
__device__ __forceinline__ void slide31(float a[32], float vold, float vnew) {
    float c_prev = (a[0] < vold) ? a[0] : a[1];
    a[0] = fminf(c_prev, vnew);
#pragma unroll
    for (int i = 1; i <= 29; ++i) {
        float ci = (a[i] < vold) ? a[i] : a[i + 1];
        float ri = fmaxf(c_prev, fminf(ci, vnew));
        a[i] = ri;
        c_prev = ci;
    }
    a[30] = fmaxf(c_prev, vnew);
}

// ───────────────────────── kernel A: harmonic (median along W) ─────────────
// 64-thread blocks, 64 rows x 32 output cols, 16.1KB smem -> 14 blocks/SM
#define A_ROWS 64
#define A_COLS 32
#define A_TW (A_COLS + 2 * RAD)  // 62
#define A_STR 63                 // odd -> conflict-free

__global__ __launch_bounds__(A_ROWS)
void hpss_harm(const float* __restrict__ S) {
    __shared__ float sm[A_ROWS * A_STR];
    const int img = blockIdx.z;
    const int h0 = blockIdx.y * A_ROWS;
    const int w0 = blockIdx.x * A_COLS;
    const float* __restrict__ Simg = S + (size_t)img * HH * WW;
    const int tid = threadIdx.x;

    for (int idx = tid; idx < A_ROWS * A_TW; idx += A_ROWS) {
        int r = idx / A_TW, c = idx - r * A_TW;
        int gh = h0 + r, gw = w0 - RAD + c;
        float v = 0.0f;
        if (gh < HH && gw >= 0 && gw < WW) v = Simg[gh * WW + gw];
        sm[r * A_STR + c] = v;
    }
    __syncthreads();

    if (h0 + tid < HH) {
        float* row = &sm[tid * A_STR];
        float a[32];
#pragma unroll
        for (int i = 0; i < 31; ++i) a[i] = row[i];
        a[31] = __int_as_float(0x7f800000);  // +INF
        sort32(a);
#pragma unroll 2
        for (int j = 0; j < A_COLS - 1; ++j) {
            float m = a[15];
            float vold = row[j];
            float vnew = row[j + KW];
            row[j] = m;            // col j is dead for later windows
            slide31(a, vold, vnew);
        }
        row[A_COLS - 1] = a[15];
    }
    __syncthreads();

    float* __restrict__ Himg = g_harm + (size_t)img * HH * WW;
    for (int idx = tid; idx < A_ROWS * A_COLS; idx += A_ROWS) {
        int r = idx >> 5, c = idx & 31;
        int gh = h0 + r;
        if (gh < HH) Himg[gh * WW + w0 + c] = sm[r * A_STR + c];
    }
}

// ─────────── kernel B: percussive (median along H) + masks ─────────────────
// 128 threads, 128 cols x 32 output rows; col data staged in smem (32.3KB)
// -> 7 blocks/SM, all loop loads are LDS or prefetched.
#define PJ 32
#define B_TH (PJ + 2 * RAD)  // 62 staged rows
#define B_STR 63             // odd -> conflict-free

__global__ __launch_bounds__(128)
void hpss_perc(const float* __restrict__ S, float* __restrict__ out, int n) {
    __shared__ float sm[128 * B_STR];
    const int img = blockIdx.z;
    const int h0  = blockIdx.y * PJ;
    const int w0  = blockIdx.x * 128;
    const int tid = threadIdx.x;
    const float* __restrict__ Simg = S + (size_t)img * HH * WW;

    // stage rows [h0-15, h0+46] of cols [w0, w0+128), transposed, zero-padded
    for (int idx = tid; idx < B_TH * 128; idx += 128) {
        int r = idx >> 7, c = idx & 127;              // coalesced over c
        int gh = h0 - RAD + r;
        float v = 0.0f;
        if (gh >= 0 && gh < HH) v = Simg[(size_t)gh * WW + w0 + c];
        sm[c * B_STR + r] = v;                        // stride 63: no conflicts
    }
    __syncthreads();

    const int w = w0 + tid;
    const float* __restrict__ colH = g_harm + (size_t)img * HH * WW + w;
    float* __restrict__ outH = out + (size_t)img * HH * WW + w;
    float* __restrict__ outP = outH + (size_t)n;
    float* col = &sm[tid * B_STR];

    float a[32];
#pragma unroll
    for (int i = 0; i < 31; ++i) a[i] = col[i];
    a[31] = __int_as_float(0x7f800000);
    sort32(a);

    float harm = colH[(size_t)h0 * WW];  // prefetch j=0

#pragma unroll 2
    for (int j = 0; j < PJ; ++j) {
        const int hh = h0 + j;
        if (hh >= HH) break;             // uniform across block
        const float perc = a[15];
        const float sv   = col[j + RAD]; // S[hh][w] via LDS

        const float h2 = harm * harm, p2 = perc * perc;
        const float inv = __fdividef(1.0f, h2 + p2);
        outH[(size_t)hh * WW] = sv * (h2 * inv);
        outP[(size_t)hh * WW] = sv * (p2 * inv);

        if (j != PJ - 1) {
            if (hh + 1 < HH) harm = colH[(size_t)(hh + 1) * WW];  // prefetch
            slide31(a, col[j], col[j + KW]);  // LDS, on-chip guaranteed
        }
    }
}

extern "C" void kernel_launch(void* const* d_in, const int* in_sizes, int n_in,
                              void* d_out, int out_size) {
    const float* S = (const float*)d_in[0];
    float* out = (float*)d_out;
    const int n = in_sizes[0];  // 4,198,400

    dim3 gA(WW / A_COLS, (HH + A_ROWS - 1) / A_ROWS, NIMG);  // 32 x 17 x 4
    hpss_harm<<<gA, A_ROWS>>>(S);
    dim3 gB(WW / 128, (HH + PJ - 1) / PJ, NIMG);             // 8 x 33 x 4
    hpss_perc<<<gB, 128>>>(S, out, n);

    (void)n_in; (void)out_size;
}